// round 1
// baseline (speedup 1.0000x reference)
#include <cuda_runtime.h>

// Quanvolution: 8192 images, 196 2x2-patches each, 4-qubit RY/CNOT circuit per patch.
// One thread per (batch, patch). 16 real amplitudes live in registers; CNOTs are
// compile-time permutations (free). Variational angles' cos/sin computed once per
// block into shared. Data-encoding trig via FMA-pipe polynomial (avoids MUFU wall).

#define NB    8192
#define NPAT  196
#define NTOT  (NB * NPAT)          // 1,605,632 = 6272 * 256 exactly
#define TPB   256

// sin/cos of t (|t| < ~1.2), degree 7/6 Taylor — err < 3e-6, FMA-pipe only.
static __device__ __forceinline__ void sc_poly(float t, float& s, float& c) {
    float u = t * t;
    c = fmaf(u, fmaf(u, fmaf(u, -1.0f/720.0f, 1.0f/24.0f), -0.5f), 1.0f);
    s = t * fmaf(u, fmaf(u, fmaf(u, -1.0f/5040.0f, 1.0f/120.0f), -1.0f/6.0f), 1.0f);
}

// amplitude index i = i0*8 + i1*4 + i2*2 + i3   (wire w -> bit (8 >> w))
template<int W>
static __device__ __forceinline__ void apply_ry(float (&a)[16], float c, float s) {
    constexpr int bit = 8 >> W;
    #pragma unroll
    for (int i = 0; i < 16; ++i) {
        if (!(i & bit)) {
            float lo = a[i], hi = a[i | bit];
            a[i]       = fmaf(c, lo, -s * hi);
            a[i | bit] = fmaf(s, lo,  c * hi);
        }
    }
}

// CNOT(ctrl C, tgt T): swap amplitudes with ctrl bit set along tgt bit.
// Pure register renaming after unroll — zero SASS.
template<int C, int T>
static __device__ __forceinline__ void apply_cnot(float (&a)[16]) {
    constexpr int cb = 8 >> C;
    constexpr int tb = 8 >> T;
    #pragma unroll
    for (int i = 0; i < 16; ++i) {
        if ((i & cb) && !(i & tb)) {
            float t = a[i];
            a[i] = a[i | tb];
            a[i | tb] = t;
        }
    }
}

__global__ void __launch_bounds__(TPB)
quanv_kernel(const float* __restrict__ x,
             const float* __restrict__ par,
             float* __restrict__ out)
{
    // cos/sin of the 8 variational half-angles, shared per block.
    // sc[2k] = cos(par[k]/2), sc[2k+1] = sin(par[k]/2), k = layer*4 + wire.
    __shared__ float sc[16];
    if (threadIdx.x < 8) {
        float s, c;
        sincosf(0.5f * par[threadIdx.x], &s, &c);
        sc[2 * threadIdx.x]     = c;
        sc[2 * threadIdx.x + 1] = s;
    }
    __syncthreads();

    int gid = blockIdx.x * TPB + threadIdx.x;   // NTOT == gridDim*TPB exactly
    int b   = gid / NPAT;
    int p   = gid - b * NPAT;
    int pr  = p / 14;
    int pc  = p - pr * 14;

    const float* img = x + b * 784 + pr * 56 + pc * 2;
    float2 t0 = *reinterpret_cast<const float2*>(img);        // x00, x01 -> wires 0,1
    float2 t1 = *reinterpret_cast<const float2*>(img + 28);   // x10, x11 -> wires 2,3

    float c0, s0, c1, s1, c2, s2, c3, s3;
    sc_poly(0.5f * t0.x, s0, c0);
    sc_poly(0.5f * t0.y, s1, c1);
    sc_poly(0.5f * t1.x, s2, c2);
    sc_poly(0.5f * t1.y, s3, c3);

    // separable encoding state: a[i] = f0(i0) f1(i1) f2(i2) f3(i3)
    float ab[4] = { c0 * c1, c0 * s1, s0 * c1, s0 * s1 };
    float cd[4] = { c2 * c3, c2 * s3, s2 * c3, s2 * s3 };
    float a[16];
    #pragma unroll
    for (int i = 0; i < 4; ++i)
        #pragma unroll
        for (int j = 0; j < 4; ++j)
            a[i * 4 + j] = ab[i] * cd[j];

    // entangling chain after encoding
    apply_cnot<0, 1>(a); apply_cnot<1, 2>(a); apply_cnot<2, 3>(a);

    // variational layers
    #pragma unroll
    for (int l = 0; l < 2; ++l) {
        apply_ry<0>(a, sc[8 * l + 0], sc[8 * l + 1]);
        apply_ry<1>(a, sc[8 * l + 2], sc[8 * l + 3]);
        apply_ry<2>(a, sc[8 * l + 4], sc[8 * l + 5]);
        apply_ry<3>(a, sc[8 * l + 6], sc[8 * l + 7]);
        apply_cnot<0, 1>(a); apply_cnot<1, 2>(a); apply_cnot<2, 3>(a);
    }

    // probabilities + shared +/- reduction tree for the 4 <Z_w>
    float pq[16];
    #pragma unroll
    for (int i = 0; i < 16; ++i) pq[i] = a[i] * a[i];

    float q[8];
    float z3 = 0.0f;
    #pragma unroll
    for (int k = 0; k < 8; ++k) {
        q[k] = pq[2 * k] + pq[2 * k + 1];
        z3  += pq[2 * k] - pq[2 * k + 1];
    }
    float r[4];
    float z2 = 0.0f;
    #pragma unroll
    for (int j = 0; j < 4; ++j) {
        r[j] = q[2 * j] + q[2 * j + 1];
        z2  += q[2 * j] - q[2 * j + 1];
    }
    float z1 = (r[0] - r[1]) + (r[2] - r[3]);
    float z0 = (r[0] + r[1]) - (r[2] + r[3]);

    *reinterpret_cast<float4*>(out + gid * 4) = make_float4(z0, z1, z2, z3);
}

extern "C" void kernel_launch(void* const* d_in, const int* in_sizes, int n_in,
                              void* d_out, int out_size)
{
    const float* x   = (const float*)d_in[0];   // (8192,1,28,28) fp32
    const float* par = (const float*)d_in[1];   // (2,4) fp32
    float* out       = (float*)d_out;           // (8192, 784) fp32
    (void)in_sizes; (void)n_in; (void)out_size;

    quanv_kernel<<<NTOT / TPB, TPB>>>(x, par, out);
}

// round 2
// speedup vs baseline: 1.0012x; 1.0012x over previous
#include <cuda_runtime.h>

// Quanvolution via packed f32x2 (Blackwell FFMA2) statevector simulation.
// One thread per (batch, patch). 16 real amplitudes packed as 8 u64 registers,
// paired along the wire-3 bit: v[r] = (a[2r], a[2r+1]), r bits = (i0,i1,i2).
// RYs on wires 0-2 are lane-wise packed butterflies; RY on wire 3 is an
// intra-register rotate; CNOT(0,1)/(1,2) are register renames; CNOT(2,3) is a
// half-swap (ALU movs). Variational cos/sin pre-packed in shared.

#define NB    8192
#define NPAT  196
#define NTOT  (NB * NPAT)          // 1,605,632 = 6272 * 256 exactly
#define TPB   256

typedef unsigned long long u64;

static __device__ __forceinline__ u64 pk2(float lo, float hi) {
    u64 r; asm("mov.b64 %0, {%1, %2};" : "=l"(r) : "f"(lo), "f"(hi)); return r;
}
static __device__ __forceinline__ void upk2(u64 v, float& lo, float& hi) {
    asm("mov.b64 {%0, %1}, %2;" : "=f"(lo), "=f"(hi) : "l"(v));
}
static __device__ __forceinline__ u64 fma2(u64 a, u64 b, u64 c) {
    u64 d; asm("fma.rn.f32x2 %0, %1, %2, %3;" : "=l"(d) : "l"(a), "l"(b), "l"(c)); return d;
}
static __device__ __forceinline__ u64 mul2(u64 a, u64 b) {
    u64 d; asm("mul.rn.f32x2 %0, %1, %2;" : "=l"(d) : "l"(a), "l"(b)); return d;
}

// broadcast compile-time constant (k, k)
#define PKC(k) pk2((k), (k))

// lane-wise packed RY butterfly: (lo,hi) <- (c*lo - s*hi, s*lo + c*hi) on both lanes
#define BF2(LO, HI, CC, SS, NSS) do {            \
    u64 _t0 = mul2((NSS), (HI));                 \
    u64 _t1 = mul2((CC),  (HI));                 \
    u64 _nl = fma2((CC), (LO), _t0);             \
    (HI) = fma2((SS), (LO), _t1);                \
    (LO) = _nl;                                  \
} while (0)

// intra-register RY (wire 3): v=(lo,hi) -> (c*lo - s*hi, s*lo + c*hi)
// = cc*v + sn*swap(v), with sn = (-s, s)
#define RY3(V, CC, SN) do {                      \
    float _l, _h; upk2((V), _l, _h);             \
    u64 _w = pk2(_h, _l);                        \
    (V) = fma2((CC), (V), mul2((SN), _w));       \
} while (0)

// intra-register half swap (CNOT target on wire 3)
#define HSWAP(V) do {                            \
    float _l, _h; upk2((V), _l, _h);             \
    (V) = pk2(_h, _l);                           \
} while (0)

// packed sin/cos of both lanes of t (|t| < 0.5): degree 7/6 Taylor, FMA pipe only
static __device__ __forceinline__ void sc_poly2(u64 t, u64& s, u64& c) {
    u64 u = mul2(t, t);
    u64 pc = fma2(u, PKC(-1.0f/720.0f), PKC(1.0f/24.0f));
    pc     = fma2(u, pc, PKC(-0.5f));
    c      = fma2(u, pc, PKC(1.0f));
    u64 ps = fma2(u, PKC(-1.0f/5040.0f), PKC(1.0f/120.0f));
    ps     = fma2(u, ps, PKC(-1.0f/6.0f));
    ps     = fma2(u, ps, PKC(1.0f));
    s      = mul2(t, ps);
}

__global__ void __launch_bounds__(TPB)
quanv_kernel(const float* __restrict__ x,
             const float* __restrict__ par,
             float* __restrict__ out)
{
    // packed variational constants: [k][0]=(c,c) [k][1]=(s,s) [k][2]=(-s,-s) [k][3]=(-s,s)
    __shared__ u64 scp[8][4];
    if (threadIdx.x < 8) {
        float s, c;
        sincosf(0.5f * par[threadIdx.x], &s, &c);
        scp[threadIdx.x][0] = pk2(c, c);
        scp[threadIdx.x][1] = pk2(s, s);
        scp[threadIdx.x][2] = pk2(-s, -s);
        scp[threadIdx.x][3] = pk2(-s, s);
    }
    __syncthreads();

    int gid = blockIdx.x * TPB + threadIdx.x;   // NTOT == gridDim*TPB exactly
    int b   = gid / NPAT;
    int p   = gid - b * NPAT;
    int pr  = p / 14;
    int pc  = p - pr * 14;

    const float* img = x + b * 784 + pr * 56 + pc * 2;
    float2 t0 = *reinterpret_cast<const float2*>(img);        // x00, x01 -> wires 0,1
    float2 t1 = *reinterpret_cast<const float2*>(img + 28);   // x10, x11 -> wires 2,3

    // packed half-angles, then packed sincos
    u64 h01 = mul2(pk2(t0.x, t0.y), PKC(0.5f));
    u64 h23 = mul2(pk2(t1.x, t1.y), PKC(0.5f));
    u64 s01, c01, s23, c23;
    sc_poly2(h01, s01, c01);
    sc_poly2(h23, s23, c23);
    float c0, c1, c2, c3, s0, s1, s2, s3;
    upk2(c01, c0, c1); upk2(s01, s0, s1);
    upk2(c23, c2, c3); upk2(s23, s2, s3);

    // separable encoding: v[r] = g_r * (c3, s3), g over wires 0..2, r bits=(i0,i1,i2)
    float t00 = c0 * c1, t01 = c0 * s1, t10 = s0 * c1, t11 = s0 * s1;
    u64 w3 = pk2(c3, s3);
    u64 v0 = mul2(pk2(t00 * c2, t00 * c2), w3);
    u64 v1 = mul2(pk2(t00 * s2, t00 * s2), w3);
    u64 v2 = mul2(pk2(t01 * c2, t01 * c2), w3);
    u64 v3 = mul2(pk2(t01 * s2, t01 * s2), w3);
    u64 v4 = mul2(pk2(t10 * c2, t10 * c2), w3);
    u64 v5 = mul2(pk2(t10 * s2, t10 * s2), w3);
    u64 v6 = mul2(pk2(t11 * c2, t11 * c2), w3);
    u64 v7 = mul2(pk2(t11 * s2, t11 * s2), w3);

    // entangling chain after encoding
    { u64 t = v4; v4 = v6; v6 = t; t = v5; v5 = v7; v7 = t; }   // CNOT(0,1)
    { u64 t = v2; v2 = v3; v3 = t; t = v6; v6 = v7; v7 = t; }   // CNOT(1,2)
    HSWAP(v1); HSWAP(v3); HSWAP(v5); HSWAP(v7);                 // CNOT(2,3)

    // variational layers
    #pragma unroll
    for (int l = 0; l < 2; ++l) {
        // RY wire 0: pairs (v_r, v_{r+4})
        { u64 cc = scp[4*l+0][0], ss = scp[4*l+0][1], ns = scp[4*l+0][2];
          BF2(v0, v4, cc, ss, ns); BF2(v1, v5, cc, ss, ns);
          BF2(v2, v6, cc, ss, ns); BF2(v3, v7, cc, ss, ns); }
        // RY wire 1: pairs (v_r, v_{r+2})
        { u64 cc = scp[4*l+1][0], ss = scp[4*l+1][1], ns = scp[4*l+1][2];
          BF2(v0, v2, cc, ss, ns); BF2(v1, v3, cc, ss, ns);
          BF2(v4, v6, cc, ss, ns); BF2(v5, v7, cc, ss, ns); }
        // RY wire 2: pairs (v_r, v_{r+1})
        { u64 cc = scp[4*l+2][0], ss = scp[4*l+2][1], ns = scp[4*l+2][2];
          BF2(v0, v1, cc, ss, ns); BF2(v2, v3, cc, ss, ns);
          BF2(v4, v5, cc, ss, ns); BF2(v6, v7, cc, ss, ns); }
        // RY wire 3: intra-register
        { u64 cc = scp[4*l+3][0], sn = scp[4*l+3][3];
          RY3(v0, cc, sn); RY3(v1, cc, sn); RY3(v2, cc, sn); RY3(v3, cc, sn);
          RY3(v4, cc, sn); RY3(v5, cc, sn); RY3(v6, cc, sn); RY3(v7, cc, sn); }
        // CNOT chain
        { u64 t = v4; v4 = v6; v6 = t; t = v5; v5 = v7; v7 = t; }
        { u64 t = v2; v2 = v3; v3 = t; t = v6; v6 = v7; v7 = t; }
        HSWAP(v1); HSWAP(v3); HSWAP(v5); HSWAP(v7);
    }

    // probabilities (packed squares) then scalar +/- reduction tree
    float pq[16];
    {
        u64 q;
        q = mul2(v0, v0); upk2(q, pq[0],  pq[1]);
        q = mul2(v1, v1); upk2(q, pq[2],  pq[3]);
        q = mul2(v2, v2); upk2(q, pq[4],  pq[5]);
        q = mul2(v3, v3); upk2(q, pq[6],  pq[7]);
        q = mul2(v4, v4); upk2(q, pq[8],  pq[9]);
        q = mul2(v5, v5); upk2(q, pq[10], pq[11]);
        q = mul2(v6, v6); upk2(q, pq[12], pq[13]);
        q = mul2(v7, v7); upk2(q, pq[14], pq[15]);
    }

    float qs[8];
    float z3 = 0.0f;
    #pragma unroll
    for (int k = 0; k < 8; ++k) {
        qs[k] = pq[2 * k] + pq[2 * k + 1];
        z3   += pq[2 * k] - pq[2 * k + 1];
    }
    float r4[4];
    float z2 = 0.0f;
    #pragma unroll
    for (int j = 0; j < 4; ++j) {
        r4[j] = qs[2 * j] + qs[2 * j + 1];
        z2   += qs[2 * j] - qs[2 * j + 1];
    }
    float z1 = (r4[0] - r4[1]) + (r4[2] - r4[3]);
    float z0 = (r4[0] + r4[1]) - (r4[2] + r4[3]);

    *reinterpret_cast<float4*>(out + gid * 4) = make_float4(z0, z1, z2, z3);
}

extern "C" void kernel_launch(void* const* d_in, const int* in_sizes, int n_in,
                              void* d_out, int out_size)
{
    const float* x   = (const float*)d_in[0];   // (8192,1,28,28) fp32
    const float* par = (const float*)d_in[1];   // (2,4) fp32
    float* out       = (float*)d_out;           // (8192, 784) fp32
    (void)in_sizes; (void)n_in; (void)out_size;

    quanv_kernel<<<NTOT / TPB, TPB>>>(x, par, out);
}

// round 3
// speedup vs baseline: 1.1830x; 1.1816x over previous
#include <cuda_runtime.h>

// Quanvolution, 2 patches per thread: f32x2 lanes = (patchA, patchB).
// 16 amplitudes in 16 u64 regs -> every CNOT chain is the compile-time Gray
// permutation v[i] <- v[i ^ (i>>1)] (zero SASS). RY butterflies use the
// 3-FMA lifting scheme (t = tan(alpha/2), s = sin(alpha)). First CNOT chain
// folded into the separable encoding build; last chain folded into the
// measurement sign patterns (prefix parities). Encoding trig on MUFU pipe.

#define NB    8192
#define PPB2  98                    // patch PAIRS per batch (196/2)
#define NTH   (NB * PPB2)           // 802,816 = 3136 * 256
#define TPB   256

typedef unsigned long long u64;

static __device__ __forceinline__ u64 pk2(float lo, float hi) {
    u64 r; asm("mov.b64 %0, {%1, %2};" : "=l"(r) : "f"(lo), "f"(hi)); return r;
}
static __device__ __forceinline__ void upk2(u64 v, float& lo, float& hi) {
    asm("mov.b64 {%0, %1}, %2;" : "=f"(lo), "=f"(hi) : "l"(v));
}
static __device__ __forceinline__ u64 fma2(u64 a, u64 b, u64 c) {
    u64 d; asm("fma.rn.f32x2 %0, %1, %2, %3;" : "=l"(d) : "l"(a), "l"(b), "l"(c)); return d;
}
static __device__ __forceinline__ u64 mul2(u64 a, u64 b) {
    u64 d; asm("mul.rn.f32x2 %0, %1, %2;" : "=l"(d) : "l"(a), "l"(b)); return d;
}
static __device__ __forceinline__ u64 add2(u64 a, u64 b) {
    u64 d; asm("add.rn.f32x2 %0, %1, %2;" : "=l"(d) : "l"(a), "l"(b)); return d;
}
static __device__ __forceinline__ u64 sub2(u64 a, u64 b) {
    u64 d; asm("sub.rn.f32x2 %0, %1, %2;" : "=l"(d) : "l"(a), "l"(b)); return d;
}

// lifting RY butterfly on packed pair (lo,hi), rotation angle alpha:
// nt = (-tan(alpha/2)) broadcast, ss = (sin alpha) broadcast.
// lo' = c*lo - s*hi ; hi' = s*lo + c*hi   (3 fma2)
template<int BIT>
static __device__ __forceinline__ void ry_wire(u64 (&v)[16], u64 nt, u64 ss) {
    #pragma unroll
    for (int i = 0; i < 16; ++i) {
        if (!(i & BIT)) {
            u64 lo = v[i], hi = v[i | BIT];
            u64 l1 = fma2(nt, hi, lo);
            u64 h2 = fma2(ss, l1, hi);
            v[i]       = fma2(nt, h2, l1);
            v[i | BIT] = h2;
        }
    }
}

// CNOT chain (0,1)(1,2)(2,3): new[i] = old[i ^ (i>>1)] — register rename only.
static __device__ __forceinline__ void gray_perm(u64 (&v)[16]) {
    u64 t[16];
    #pragma unroll
    for (int i = 0; i < 16; ++i) t[i] = v[i ^ (i >> 1)];
    #pragma unroll
    for (int i = 0; i < 16; ++i) v[i] = t[i];
}

__global__ void __launch_bounds__(TPB)
quanv_kernel(const float* __restrict__ x,
             const float* __restrict__ par,
             float* __restrict__ out)
{
    // lifting constants per variational RY k = layer*4 + wire:
    // rotation angle alpha = par[k]/2 -> nt = -tan(par[k]/4), ss = sin(par[k]/2)
    __shared__ u64 sh_nt[8], sh_ss[8];
    if (threadIdx.x < 8) {
        float th = par[threadIdx.x];
        float t  = tanf(0.25f * th);
        float s  = sinf(0.5f * th);
        sh_nt[threadIdx.x] = pk2(-t, -t);
        sh_ss[threadIdx.x] = pk2(s, s);
    }
    __syncthreads();

    int gid = blockIdx.x * TPB + threadIdx.x;    // NTH == gridDim*TPB exactly
    int b   = gid / PPB2;
    int pp  = gid - b * PPB2;                    // patch-pair index 0..97
    int pr  = pp / 7;                            // patch row 0..13
    int pj  = pp - pr * 7;                       // pair-column 0..6 (covers pc=2pj, 2pj+1)

    // two adjacent 2x2 patches = 2 coalesced float4 loads
    const float4* src = reinterpret_cast<const float4*>(x + b * 784 + pr * 56 + pj * 4);
    float4 r0 = src[0];   // row 2pr  : A0 A1 B0 B1
    float4 r1 = src[7];   // row 2pr+1: A2 A3 B2 B3

    // encoding trig on MUFU pipe (lanes = patches)
    float h;
    h = 0.5f * r0.x; float cA0 = __cosf(h), sA0 = __sinf(h);
    h = 0.5f * r0.y; float cA1 = __cosf(h), sA1 = __sinf(h);
    h = 0.5f * r1.x; float cA2 = __cosf(h), sA2 = __sinf(h);
    h = 0.5f * r1.y; float cA3 = __cosf(h), sA3 = __sinf(h);
    h = 0.5f * r0.z; float cB0 = __cosf(h), sB0 = __sinf(h);
    h = 0.5f * r0.w; float cB1 = __cosf(h), sB1 = __sinf(h);
    h = 0.5f * r1.z; float cB2 = __cosf(h), sB2 = __sinf(h);
    h = 0.5f * r1.w; float cB3 = __cosf(h), sB3 = __sinf(h);

    u64 c0 = pk2(cA0, cB0), s0 = pk2(sA0, sB0);
    u64 c1 = pk2(cA1, cB1), s1 = pk2(sA1, sB1);
    u64 c2 = pk2(cA2, cB2), s2 = pk2(sA2, sB2);
    u64 c3 = pk2(cA3, cB3), s3 = pk2(sA3, sB3);

    // separable encoding with FIRST CNOT chain pre-folded:
    // v[i] = g0[i0] * g1[i1^i0] * g2[i2^i1] * g3[i3^i2]
    u64 P01[4];                      // [i0*2+i1] = g0[i0]*g1[i1^i0]
    P01[0] = mul2(c0, c1);
    P01[1] = mul2(c0, s1);
    P01[2] = mul2(s0, s1);
    P01[3] = mul2(s0, c1);
    u64 Q[4];                        // [x*2+y] = g2[x]*g3[y]
    Q[0] = mul2(c2, c3);
    Q[1] = mul2(c2, s3);
    Q[2] = mul2(s2, c3);
    Q[3] = mul2(s2, s3);

    u64 v[16];
    #pragma unroll
    for (int i = 0; i < 16; ++i) {
        int i0 = (i >> 3) & 1, i1 = (i >> 2) & 1, i2 = (i >> 1) & 1, i3 = i & 1;
        v[i] = mul2(P01[i0 * 2 + i1], Q[(i2 ^ i1) * 2 + (i3 ^ i2)]);
    }

    // variational layer 1
    ry_wire<8>(v, sh_nt[0], sh_ss[0]);
    ry_wire<4>(v, sh_nt[1], sh_ss[1]);
    ry_wire<2>(v, sh_nt[2], sh_ss[2]);
    ry_wire<1>(v, sh_nt[3], sh_ss[3]);
    gray_perm(v);                    // middle CNOT chain: free rename
    // variational layer 2
    ry_wire<8>(v, sh_nt[4], sh_ss[4]);
    ry_wire<4>(v, sh_nt[5], sh_ss[5]);
    ry_wire<2>(v, sh_nt[6], sh_ss[6]);
    ry_wire<1>(v, sh_nt[7], sh_ss[7]);
    // final CNOT chain folded into measurement signs:
    // z0: (-1)^{i0}, z1: (-1)^{i0+i1}, z2: (-1)^{i0+i1+i2}, z3: full parity

    u64 p[16];
    #pragma unroll
    for (int i = 0; i < 16; ++i) p[i] = mul2(v[i], v[i]);

    u64 s1a[8], d1a[8];
    #pragma unroll
    for (int k = 0; k < 8; ++k) {
        s1a[k] = add2(p[2 * k], p[2 * k + 1]);
        d1a[k] = sub2(p[2 * k], p[2 * k + 1]);
    }
    // z3 = sum (-1)^{parity(k)} d1a[k]
    u64 z3 = sub2(sub2(sub2(d1a[0], d1a[1]), sub2(d1a[2], d1a[3])),
                  sub2(sub2(d1a[4], d1a[5]), sub2(d1a[6], d1a[7])));

    u64 s2a[4], e[4];
    #pragma unroll
    for (int j = 0; j < 4; ++j) {
        s2a[j] = add2(s1a[2 * j], s1a[2 * j + 1]);
        e[j]   = sub2(s1a[2 * j], s1a[2 * j + 1]);
    }
    u64 z2 = sub2(sub2(e[0], e[1]), sub2(e[2], e[3]));

    u64 U0 = add2(s2a[0], s2a[1]), U1 = add2(s2a[2], s2a[3]);
    u64 E0 = sub2(s2a[0], s2a[1]), E1 = sub2(s2a[2], s2a[3]);
    u64 z1 = sub2(E0, E1);
    u64 z0 = sub2(U0, U1);

    float za0, zb0, za1, zb1, za2, zb2, za3, zb3;
    upk2(z0, za0, zb0); upk2(z1, za1, zb1);
    upk2(z2, za2, zb2); upk2(z3, za3, zb3);

    // output: patches (pr*14 + 2pj) and (pr*14 + 2pj + 1) of batch b, 4 floats each
    float4* o = reinterpret_cast<float4*>(out + ((size_t)b * 196 + pr * 14 + 2 * pj) * 4);
    o[0] = make_float4(za0, za1, za2, za3);
    o[1] = make_float4(zb0, zb1, zb2, zb3);
}

extern "C" void kernel_launch(void* const* d_in, const int* in_sizes, int n_in,
                              void* d_out, int out_size)
{
    const float* x   = (const float*)d_in[0];   // (8192,1,28,28) fp32
    const float* par = (const float*)d_in[1];   // (2,4) fp32
    float* out       = (float*)d_out;           // (8192, 784) fp32
    (void)in_sizes; (void)n_in; (void)out_size;

    quanv_kernel<<<NTH / TPB, TPB>>>(x, par, out);
}